// round 11
// baseline (speedup 1.0000x reference)
#include <cuda_runtime.h>
#include <cuda_bf16.h>
#include <cstdint>
#include <cstring>

// ============================================================================
// Problem constants
// ============================================================================
#define BD     16384
#define HID    512
#define IND    256
#define KPRJ   768          // [u_hi | u_lo | u_hi] split-projection K
#define NSTEPS 8
#define NN     ((size_t)BD * (size_t)HID)

// ============================================================================
// Device scratch (__device__ globals: allocation-free rule)
// ============================================================================
__device__ float         g_S  [NN];            // fp32 RK state
__device__ __nv_bfloat16 g_Sbf[NN];            // bf16 stage input
__device__ __nv_bfloat16 g_H1 [NN];
__device__ __nv_bfloat16 g_H2 [NN];
__device__ __nv_bfloat16 g_Karr[5 * NN];       // k1..k5 (k6 consumed in-register)
__device__ __nv_bfloat16 g_U  [(size_t)BD * KPRJ];
__device__ __nv_bfloat16 g_W1t[HID * HID];     // [N,K] transposed weights (bf16)
__device__ __nv_bfloat16 g_W2t[HID * HID];
__device__ __nv_bfloat16 g_W3t[HID * HID];
__device__ __nv_bfloat16 g_Wpt[HID * KPRJ];

// ============================================================================
// PTX helpers (sm_80-class only: compiles under compute_103 virtual arch)
// ============================================================================
#define CP_ASYNC16(saddr, gptr) \
    asm volatile("cp.async.cg.shared.global [%0], [%1], 16;" \
        :: "r"(saddr), "l"(gptr) : "memory")

#define CP_COMMIT() asm volatile("cp.async.commit_group;" ::: "memory")

#define CP_WAIT(n)  asm volatile("cp.async.wait_group %0;" :: "n"(n) : "memory")

#define LDSM_X4(r, addr) \
    asm volatile("ldmatrix.sync.aligned.m8n8.x4.shared.b16 {%0,%1,%2,%3}, [%4];" \
        : "=r"((r)[0]), "=r"((r)[1]), "=r"((r)[2]), "=r"((r)[3]) : "r"(addr))

__device__ __forceinline__ uint32_t smem_to_u32(const void* smem_ptr) {
    uint32_t addr;
    asm("{ .reg .u64 tmp; cvta.to.shared.u64 tmp, %1; cvt.u32.u64 %0, tmp; }"
        : "=r"(addr) : "l"(smem_ptr));
    return addr;
}

__device__ __forceinline__ void mma_bf16(float* d, const uint32_t* a,
                                         uint32_t b0, uint32_t b1) {
    asm volatile(
        "mma.sync.aligned.m16n8k16.row.col.f32.bf16.bf16.f32 "
        "{%0,%1,%2,%3}, {%4,%5,%6,%7}, {%8,%9}, {%0,%1,%2,%3};"
        : "+f"(d[0]), "+f"(d[1]), "+f"(d[2]), "+f"(d[3])
        : "r"(a[0]), "r"(a[1]), "r"(a[2]), "r"(a[3]), "r"(b0), "r"(b1));
}

__device__ __forceinline__ float tanh_fast(float x) {
    float y;
    asm("tanh.approx.f32 %0, %1;" : "=f"(y) : "f"(x));
    return y;
}

__device__ __forceinline__ uint32_t packbf(float a, float b) {
    __nv_bfloat162 t = __floats2bfloat162_rn(a, b);
    return *reinterpret_cast<uint32_t*>(&t);
}

// SW128 xor swizzle on a tile-relative byte offset (rows of 128 bytes)
__device__ __forceinline__ uint32_t swz(uint32_t off) {
    return off ^ ((off >> 3) & 0x70u);
}

// ============================================================================
// Fused epilogue parameters
// ============================================================================
struct EpiParams {
    int   mode;          // 0 = tanh->bf16, 1 = proj (S=acc+bias+y), 2 = k-stage
    int   nprev;         // k-stage: number of previous k's
    int   write_state;   // k-stage: write fp32 state (j==6)
    float h;
    const float* bias;
    const float* yin;    // proj: y input
    const float* S_in;   // k-stage: base state
    float*       S_out;  // proj: g_S; k-stage j==6: g_S or d_out
    __nv_bfloat16*       out_bf;   // next-stage input / hidden activation
    __nv_bfloat16*       k_out;    // k-stage: store k_j (null for j==6)
    const __nv_bfloat16* kp[5];
    float c[6];          // c[0..nprev-1] prev-k coefs, c[nprev] current-k coef
};

// ============================================================================
// bf16 GEMM via mma.sync: D[16384,512] = A[16384,K] @ Wt[512,K]^T, fused epi
// grid (128, 4): CTA tile M=128 x N=128.  256 threads = 8 warps (4 M x 2 N),
// warp tile 32x64.  4-stage cp.async pipeline, K chunks of 64.
// ============================================================================
#define STAGES   4
#define SM_STAGE 32768        // A tile 16KB + B tile 16KB
#define SMEM_DYN (STAGES * SM_STAGE + 1024)

__global__ __launch_bounds__(256)
void ode_gemm(const __nv_bfloat16* __restrict__ A,
              const __nv_bfloat16* __restrict__ Bw,
              int Ktot, EpiParams ep) {
    extern __shared__ char smem_raw[];
    const uint32_t sb = (smem_to_u32(smem_raw) + 1023u) & ~1023u;

    const int tid  = threadIdx.x;
    const int lane = tid & 31;
    const int wid  = tid >> 5;
    const int warp_m = wid >> 1;          // 0..3
    const int warp_n = wid & 1;           // 0..1
    const int mtile = blockIdx.x;
    const int ntile = blockIdx.y;

    const int KT = Ktot >> 6;             // 64-wide K chunks (8 or 12)

    // per-thread cp.async coords: thread -> (row = tid>>3 [+32*r], seg = tid&7)
    const int lrow = tid >> 3;
    const int lseg = tid & 7;
    const __nv_bfloat16* Abase = A  + (size_t)(mtile * 128) * Ktot + lseg * 8;
    const __nv_bfloat16* Bbase = Bw + (size_t)(ntile * 128) * Ktot + lseg * 8;

    // ---- async stage loader: 4 A rows + 4 B rows of 16B each ----
    auto issue = [&](int kt) {
        const uint32_t stg = sb + (uint32_t)(kt % STAGES) * SM_STAGE;
        const int k0 = kt * 64;
#pragma unroll
        for (int r = 0; r < 4; ++r) {
            const int row = lrow + r * 32;
            const uint32_t off = swz((uint32_t)(row * 128 + lseg * 16));
            CP_ASYNC16(stg + off,          Abase + (size_t)row * Ktot + k0);
            CP_ASYNC16(stg + 16384 + off,  Bbase + (size_t)row * Ktot + k0);
        }
    };

    float d[2][8][4];
#pragma unroll
    for (int mi = 0; mi < 2; ++mi)
#pragma unroll
        for (int ni = 0; ni < 8; ++ni)
#pragma unroll
            for (int e = 0; e < 4; ++e) d[mi][ni][e] = 0.0f;

    // ---- prologue ----
#pragma unroll
    for (int s = 0; s < STAGES - 1; ++s) {
        issue(s);
        CP_COMMIT();
    }

    // precomputed ldmatrix lane offsets
    const int a_rl = ((lane >> 3) & 1) * 8 + (lane & 7);   // A: row within 16
    const int a_sl = (lane >> 4);                          // A: +seg
    const int b_rl = ((lane >> 4) & 1) * 8 + (lane & 7);   // B: row within 16
    const int b_sl = ((lane >> 3) & 1);                    // B: +seg

    // ---- mainloop ----
    for (int kt = 0; kt < KT; ++kt) {
        if (kt + STAGES - 1 < KT) issue(kt + STAGES - 1);
        CP_COMMIT();
        CP_WAIT(STAGES - 1);                // stage kt resident
        __syncthreads();

        const uint32_t stg = sb + (uint32_t)(kt % STAGES) * SM_STAGE;
        const uint32_t aT = stg, bT = stg + 16384;

#pragma unroll
        for (int ks = 0; ks < 4; ++ks) {
            uint32_t a_fr[2][4];
#pragma unroll
            for (int mi = 0; mi < 2; ++mi) {
                const int row = warp_m * 32 + mi * 16 + a_rl;
                const int seg = ks * 2 + a_sl;
                LDSM_X4(a_fr[mi], aT + swz((uint32_t)(row * 128 + seg * 16)));
            }
            uint32_t b_fr[4][4];
#pragma unroll
            for (int nb = 0; nb < 4; ++nb) {
                const int nrow = warp_n * 64 + nb * 16 + b_rl;
                const int seg  = ks * 2 + b_sl;
                LDSM_X4(b_fr[nb], bT + swz((uint32_t)(nrow * 128 + seg * 16)));
            }
#pragma unroll
            for (int mi = 0; mi < 2; ++mi)
#pragma unroll
                for (int nb = 0; nb < 4; ++nb) {
                    mma_bf16(d[mi][nb * 2],     a_fr[mi], b_fr[nb][0], b_fr[nb][1]);
                    mma_bf16(d[mi][nb * 2 + 1], a_fr[mi], b_fr[nb][2], b_fr[nb][3]);
                }
        }
        __syncthreads();
    }

    // ---- fused epilogue ----
    {
        const int tig = lane & 3;
        const int grp = lane >> 2;
        const int col0 = ntile * 128 + warp_n * 64;
        const int rowbase = mtile * 128 + warp_m * 32;

        // bias pairs per ni
        float bias0[8], bias1[8];
#pragma unroll
        for (int ni = 0; ni < 8; ++ni) {
            const int c = col0 + ni * 8 + 2 * tig;
            bias0[ni] = __ldg(ep.bias + c);
            bias1[ni] = __ldg(ep.bias + c + 1);
        }

        const float ccur = ep.c[ep.nprev];
        const float h = ep.h;

#pragma unroll
        for (int mi = 0; mi < 2; ++mi)
#pragma unroll
            for (int half = 0; half < 2; ++half) {
                const int r = rowbase + mi * 16 + grp + half * 8;
                const size_t rb = (size_t)r * HID;
#pragma unroll
                for (int ni = 0; ni < 8; ++ni) {
                    const int c = col0 + ni * 8 + 2 * tig;
                    const size_t off = rb + c;
                    float v0 = d[mi][ni][half * 2 + 0] + bias0[ni];
                    float v1 = d[mi][ni][half * 2 + 1] + bias1[ni];

                    if (ep.mode == 0) {
                        *reinterpret_cast<uint32_t*>(ep.out_bf + off) =
                            packbf(tanh_fast(v0), tanh_fast(v1));
                    } else if (ep.mode == 1) {
                        const float2 yv = *reinterpret_cast<const float2*>(ep.yin + off);
                        v0 += yv.x; v1 += yv.y;
                        *reinterpret_cast<float2*>(ep.S_out + off) = make_float2(v0, v1);
                        *reinterpret_cast<uint32_t*>(ep.out_bf + off) = packbf(v0, v1);
                    } else {
                        const float2 sv = *reinterpret_cast<const float2*>(ep.S_in + off);
                        float a0 = ccur * v0, a1 = ccur * v1;
                        for (int q = 0; q < 5; ++q) {
                            if (q >= ep.nprev) break;
                            __nv_bfloat162 kk;
                            *reinterpret_cast<uint32_t*>(&kk) =
                                *reinterpret_cast<const uint32_t*>(ep.kp[q] + off);
                            const float cq = ep.c[q];
                            a0 += cq * __bfloat162float(kk.x);
                            a1 += cq * __bfloat162float(kk.y);
                        }
                        const float z0 = sv.x + h * a0;
                        const float z1 = sv.y + h * a1;
                        if (ep.k_out)
                            *reinterpret_cast<uint32_t*>(ep.k_out + off) = packbf(v0, v1);
                        *reinterpret_cast<uint32_t*>(ep.out_bf + off) = packbf(z0, z1);
                        if (ep.write_state)
                            *reinterpret_cast<float2*>(ep.S_out + off) = make_float2(z0, z1);
                    }
                }
            }
    }
}

// ============================================================================
// Prep kernels
// ============================================================================
__global__ void prep_w(const float* __restrict__ Wp, const float* __restrict__ W1,
                       const float* __restrict__ W2, const float* __restrict__ W3) {
    int idx = blockIdx.x * blockDim.x + threadIdx.x;
    if (idx < HID * HID) {
        int n = idx / HID, k = idx % HID;
        g_W1t[idx] = __float2bfloat16_rn(W1[k * HID + n]);
        g_W2t[idx] = __float2bfloat16_rn(W2[k * HID + n]);
        g_W3t[idx] = __float2bfloat16_rn(W3[k * HID + n]);
    }
    if (idx < HID * KPRJ) {
        int n = idx / KPRJ, j = idx % KPRJ;
        int ksrc = (j < IND) ? j : (j < 2 * IND) ? (j - IND) : (j - 2 * IND);
        float w = Wp[ksrc * HID + n];
        __nv_bfloat16 hi = __float2bfloat16_rn(w);
        if (j < 2 * IND)
            g_Wpt[idx] = hi;                                            // hi segments
        else
            g_Wpt[idx] = __float2bfloat16_rn(w - __bfloat162float(hi)); // lo segment
    }
}

__global__ void prep_u(const float* __restrict__ u) {
    int idx = blockIdx.x * blockDim.x + threadIdx.x;
    if (idx >= BD * IND) return;
    int row = idx / IND, c = idx % IND;
    float x = u[idx];
    __nv_bfloat16 hi = __float2bfloat16_rn(x);
    __nv_bfloat16 lo = __float2bfloat16_rn(x - __bfloat162float(hi));
    size_t base = (size_t)row * KPRJ;
    g_U[base + c]           = hi;
    g_U[base + IND + c]     = lo;
    g_U[base + 2 * IND + c] = hi;
}

// ============================================================================
// Host: 2 prep + 145 GEMM launches; final stage writes d_out directly
// ============================================================================
extern "C" void kernel_launch(void* const* d_in, const int* in_sizes, int n_in,
                              void* d_out, int out_size) {
    const float* y  = (const float*)d_in[0];
    const float* u  = (const float*)d_in[1];
    const float* Wp = (const float*)d_in[2];
    const float* bp = (const float*)d_in[3];
    const float* W1 = (const float*)d_in[4];
    const float* b1 = (const float*)d_in[5];
    const float* W2 = (const float*)d_in[6];
    const float* b2 = (const float*)d_in[7];
    const float* W3 = (const float*)d_in[8];
    const float* b3 = (const float*)d_in[9];
    float* out = (float*)d_out;

    cudaFuncSetAttribute(ode_gemm, cudaFuncAttributeMaxDynamicSharedMemorySize, SMEM_DYN);

    void* pv;
    cudaGetSymbolAddress(&pv, g_S);    float* S             = (float*)pv;
    cudaGetSymbolAddress(&pv, g_Sbf);  __nv_bfloat16* Sbf   = (__nv_bfloat16*)pv;
    cudaGetSymbolAddress(&pv, g_H1);   __nv_bfloat16* H1    = (__nv_bfloat16*)pv;
    cudaGetSymbolAddress(&pv, g_H2);   __nv_bfloat16* H2    = (__nv_bfloat16*)pv;
    cudaGetSymbolAddress(&pv, g_Karr); __nv_bfloat16* Kb    = (__nv_bfloat16*)pv;
    cudaGetSymbolAddress(&pv, g_U);    __nv_bfloat16* U     = (__nv_bfloat16*)pv;
    cudaGetSymbolAddress(&pv, g_W1t);  __nv_bfloat16* W1t   = (__nv_bfloat16*)pv;
    cudaGetSymbolAddress(&pv, g_W2t);  __nv_bfloat16* W2t   = (__nv_bfloat16*)pv;
    cudaGetSymbolAddress(&pv, g_W3t);  __nv_bfloat16* W3t   = (__nv_bfloat16*)pv;
    cudaGetSymbolAddress(&pv, g_Wpt);  __nv_bfloat16* Wpt   = (__nv_bfloat16*)pv;

    prep_w<<<(HID * KPRJ + 255) / 256, 256>>>(Wp, W1, W2, W3);
    prep_u<<<(BD * IND + 255) / 256, 256>>>(u);

    const dim3 grid(128, 4);

    // Projection: S = y + u@Wp + bp  (exact via hi/lo split, K=768)
    {
        EpiParams e; memset(&e, 0, sizeof(e));
        e.mode = 1; e.bias = bp; e.yin = y; e.S_out = S; e.out_bf = Sbf;
        ode_gemm<<<grid, 256, SMEM_DYN>>>(U, Wpt, KPRJ, e);
    }

    const float h = (float)(0.1 / 8.0);
    // Row j-1: stage-combine coefs after computing k_j (row 6 = 5th-order B weights)
    static const float RKC[6][6] = {
        {1.0f/5, 0, 0, 0, 0, 0},
        {3.0f/40, 9.0f/40, 0, 0, 0, 0},
        {44.0f/45, -56.0f/15, 32.0f/9, 0, 0, 0},
        {19372.0f/6561, -25360.0f/2187, 64448.0f/6561, -212.0f/729, 0, 0},
        {9017.0f/3168, -355.0f/33, 46732.0f/5247, 49.0f/176, -5103.0f/18656, 0},
        {35.0f/384, 0.0f, 500.0f/1113, 125.0f/192, -2187.0f/6784, 11.0f/84},
    };

    for (int st = 0; st < NSTEPS; ++st) {
        for (int j = 1; j <= 6; ++j) {
            // Layer 1: tanh(Sbf @ W1 + b1) -> H1
            {
                EpiParams e; memset(&e, 0, sizeof(e));
                e.mode = 0; e.bias = b1; e.out_bf = H1;
                ode_gemm<<<grid, 256, SMEM_DYN>>>(Sbf, W1t, HID, e);
            }
            // Layer 2: tanh(H1 @ W2 + b2) -> H2
            {
                EpiParams e; memset(&e, 0, sizeof(e));
                e.mode = 0; e.bias = b2; e.out_bf = H2;
                ode_gemm<<<grid, 256, SMEM_DYN>>>(H1, W2t, HID, e);
            }
            // Layer 3: k_j = H2 @ W3 + b3, fused RK stage combine
            {
                EpiParams e; memset(&e, 0, sizeof(e));
                e.mode = 2; e.bias = b3; e.h = h;
                e.S_in = S; e.out_bf = Sbf;
                e.nprev = j - 1;
                for (int q = 0; q < 5; ++q) e.kp[q] = Kb + (size_t)q * NN;
                for (int q = 0; q < 6; ++q) e.c[q] = RKC[j - 1][q];
                e.k_out = (j <= 5) ? (Kb + (size_t)(j - 1) * NN) : (__nv_bfloat16*)0;
                if (j == 6) {
                    e.write_state = 1;
                    e.S_out = (st == NSTEPS - 1) ? out : S;
                }
                ode_gemm<<<grid, 256, SMEM_DYN>>>(H2, W3t, HID, e);
            }
        }
    }
    (void)in_sizes; (void)n_in; (void)out_size;
}

// round 12
// speedup vs baseline: 1.3388x; 1.3388x over previous
#include <cuda_runtime.h>
#include <cuda_bf16.h>
#include <cstdint>
#include <cstring>

// ============================================================================
// Problem constants
// ============================================================================
#define BD     16384
#define HID    512
#define IND    256
#define KPRJ   768          // [u_hi | u_lo | u_hi] split-projection K
#define NSTEPS 8
#define NN     ((size_t)BD * (size_t)HID)

// ============================================================================
// Device scratch (__device__ globals: allocation-free rule)
// ============================================================================
__device__ float         g_S  [NN];            // fp32 RK state
__device__ __nv_bfloat16 g_Sbf[NN];            // bf16 stage input
__device__ __nv_bfloat16 g_H1 [NN];
__device__ __nv_bfloat16 g_H2 [NN];
__device__ __nv_bfloat16 g_Karr[5 * NN];       // k1..k5 (k6 consumed in-register)
__device__ __nv_bfloat16 g_U  [(size_t)BD * KPRJ];
__device__ __nv_bfloat16 g_W1t[HID * HID];     // [N,K] transposed weights (bf16)
__device__ __nv_bfloat16 g_W2t[HID * HID];
__device__ __nv_bfloat16 g_W3t[HID * HID];
__device__ __nv_bfloat16 g_Wpt[HID * KPRJ];

// ============================================================================
// PTX helpers (sm_80-class only: compiles under compute_103 virtual arch)
// ============================================================================
#define CP_ASYNC16(saddr, gptr) \
    asm volatile("cp.async.cg.shared.global [%0], [%1], 16;" \
        :: "r"(saddr), "l"(gptr) : "memory")

#define CP_COMMIT() asm volatile("cp.async.commit_group;" ::: "memory")

#define CP_WAIT(n)  asm volatile("cp.async.wait_group %0;" :: "n"(n) : "memory")

#define LDSM_X4(r, addr) \
    asm volatile("ldmatrix.sync.aligned.m8n8.x4.shared.b16 {%0,%1,%2,%3}, [%4];" \
        : "=r"((r)[0]), "=r"((r)[1]), "=r"((r)[2]), "=r"((r)[3]) : "r"(addr))

__device__ __forceinline__ uint32_t smem_to_u32(const void* smem_ptr) {
    uint32_t addr;
    asm("{ .reg .u64 tmp; cvta.to.shared.u64 tmp, %1; cvt.u32.u64 %0, tmp; }"
        : "=r"(addr) : "l"(smem_ptr));
    return addr;
}

__device__ __forceinline__ void mma_bf16(float* d, const uint32_t* a,
                                         uint32_t b0, uint32_t b1) {
    asm volatile(
        "mma.sync.aligned.m16n8k16.row.col.f32.bf16.bf16.f32 "
        "{%0,%1,%2,%3}, {%4,%5,%6,%7}, {%8,%9}, {%0,%1,%2,%3};"
        : "+f"(d[0]), "+f"(d[1]), "+f"(d[2]), "+f"(d[3])
        : "r"(a[0]), "r"(a[1]), "r"(a[2]), "r"(a[3]), "r"(b0), "r"(b1));
}

__device__ __forceinline__ float tanh_fast(float x) {
    float y;
    asm("tanh.approx.f32 %0, %1;" : "=f"(y) : "f"(x));
    return y;
}

__device__ __forceinline__ uint32_t packbf(float a, float b) {
    __nv_bfloat162 t = __floats2bfloat162_rn(a, b);
    return *reinterpret_cast<uint32_t*>(&t);
}

// SW128 xor swizzle on a tile-relative byte offset (rows of 128 bytes)
__device__ __forceinline__ uint32_t swz(uint32_t off) {
    return off ^ ((off >> 3) & 0x70u);
}

// ============================================================================
// Fused epilogue parameters
// ============================================================================
struct EpiParams {
    int   mode;          // 0 = tanh->bf16, 1 = proj (S=acc+bias+y), 2 = k-stage
    int   nprev;         // k-stage: number of previous k's
    int   write_state;   // k-stage: write fp32 state (j==6)
    float h;
    const float* bias;
    const float* yin;    // proj: y input
    const float* S_in;   // k-stage: base state
    float*       S_out;  // proj: g_S; k-stage j==6: g_S or d_out
    __nv_bfloat16*       out_bf;   // next-stage input / hidden activation
    __nv_bfloat16*       k_out;    // k-stage: store k_j (null for j==6)
    const __nv_bfloat16* kp[5];
    float c[6];          // c[0..nprev-1] prev-k coefs, c[nprev] current-k coef
};

// ============================================================================
// bf16 GEMM via mma.sync: D[16384,512] = A[16384,K] @ Wt[512,K]^T, fused epi
// grid (128, 4): CTA tile M=128 x N=128.  256 threads = 8 warps (4 M x 2 N),
// warp tile 32x64.  3-stage cp.async pipeline, K chunks of 64, 2 CTAs/SM.
// ============================================================================
#define STAGES   3
#define SM_STAGE 32768        // A tile 16KB + B tile 16KB
#define SMEM_DYN (STAGES * SM_STAGE + 1024)

__global__ __launch_bounds__(256, 2)
void ode_gemm(const __nv_bfloat16* __restrict__ A,
              const __nv_bfloat16* __restrict__ Bw,
              int Ktot, EpiParams ep) {
    extern __shared__ char smem_raw[];
    const uint32_t sb = (smem_to_u32(smem_raw) + 1023u) & ~1023u;

    const int tid  = threadIdx.x;
    const int lane = tid & 31;
    const int wid  = tid >> 5;
    const int warp_m = wid >> 1;          // 0..3
    const int warp_n = wid & 1;           // 0..1
    const int mtile = blockIdx.x;
    const int ntile = blockIdx.y;

    const int KT = Ktot >> 6;             // 64-wide K chunks (8 or 12)

    // per-thread cp.async coords: thread -> (row = tid>>3 [+32*r], seg = tid&7)
    const int lrow = tid >> 3;
    const int lseg = tid & 7;
    const __nv_bfloat16* Abase = A  + (size_t)(mtile * 128) * Ktot + lseg * 8;
    const __nv_bfloat16* Bbase = Bw + (size_t)(ntile * 128) * Ktot + lseg * 8;

    // ---- async stage loader: 4 A rows + 4 B rows of 16B each ----
    auto issue = [&](int kt) {
        const uint32_t stg = sb + (uint32_t)(kt % STAGES) * SM_STAGE;
        const int k0 = kt * 64;
#pragma unroll
        for (int r = 0; r < 4; ++r) {
            const int row = lrow + r * 32;
            const uint32_t off = swz((uint32_t)(row * 128 + lseg * 16));
            CP_ASYNC16(stg + off,          Abase + (size_t)row * Ktot + k0);
            CP_ASYNC16(stg + 16384 + off,  Bbase + (size_t)row * Ktot + k0);
        }
    };

    float d[2][8][4];
#pragma unroll
    for (int mi = 0; mi < 2; ++mi)
#pragma unroll
        for (int ni = 0; ni < 8; ++ni)
#pragma unroll
            for (int e = 0; e < 4; ++e) d[mi][ni][e] = 0.0f;

    // ---- prologue: stages 0..STAGES-2 in flight ----
#pragma unroll
    for (int s = 0; s < STAGES - 1; ++s) {
        issue(s);
        CP_COMMIT();
    }

    // precomputed ldmatrix lane offsets
    const int a_rl = ((lane >> 3) & 1) * 8 + (lane & 7);   // A: row within 16
    const int a_sl = (lane >> 4);                          // A: +seg
    const int b_rl = ((lane >> 4) & 1) * 8 + (lane & 7);   // B: row within 16
    const int b_sl = ((lane >> 3) & 1);                    // B: +seg

    // ---- mainloop: wait -> sync -> prefetch next -> compute (1 sync/iter) ----
    for (int kt = 0; kt < KT; ++kt) {
        CP_WAIT(STAGES - 2);                // commit group kt complete
        __syncthreads();                    // publish stage kt; all reads of the
                                            // stage about to be overwritten done
        if (kt + STAGES - 1 < KT) issue(kt + STAGES - 1);
        CP_COMMIT();                        // unconditional: uniform accounting

        const uint32_t stg = sb + (uint32_t)(kt % STAGES) * SM_STAGE;
        const uint32_t aT = stg, bT = stg + 16384;

#pragma unroll
        for (int ks = 0; ks < 4; ++ks) {
            uint32_t a_fr[2][4];
#pragma unroll
            for (int mi = 0; mi < 2; ++mi) {
                const int row = warp_m * 32 + mi * 16 + a_rl;
                const int seg = ks * 2 + a_sl;
                LDSM_X4(a_fr[mi], aT + swz((uint32_t)(row * 128 + seg * 16)));
            }
            uint32_t b_fr[4][4];
#pragma unroll
            for (int nb = 0; nb < 4; ++nb) {
                const int nrow = warp_n * 64 + nb * 16 + b_rl;
                const int seg  = ks * 2 + b_sl;
                LDSM_X4(b_fr[nb], bT + swz((uint32_t)(nrow * 128 + seg * 16)));
            }
#pragma unroll
            for (int mi = 0; mi < 2; ++mi)
#pragma unroll
                for (int nb = 0; nb < 4; ++nb) {
                    mma_bf16(d[mi][nb * 2],     a_fr[mi], b_fr[nb][0], b_fr[nb][1]);
                    mma_bf16(d[mi][nb * 2 + 1], a_fr[mi], b_fr[nb][2], b_fr[nb][3]);
                }
        }
        __syncthreads();                    // stage kt fully consumed before next
                                            // iteration's overwrite of stage kt+? 
    }

    // ---- fused epilogue ----
    {
        const int tig = lane & 3;
        const int grp = lane >> 2;
        const int col0 = ntile * 128 + warp_n * 64;
        const int rowbase = mtile * 128 + warp_m * 32;

        // bias pairs per ni
        float bias0[8], bias1[8];
#pragma unroll
        for (int ni = 0; ni < 8; ++ni) {
            const int c = col0 + ni * 8 + 2 * tig;
            bias0[ni] = __ldg(ep.bias + c);
            bias1[ni] = __ldg(ep.bias + c + 1);
        }

        const float ccur = ep.c[ep.nprev];
        const float h = ep.h;

#pragma unroll
        for (int mi = 0; mi < 2; ++mi)
#pragma unroll
            for (int half = 0; half < 2; ++half) {
                const int r = rowbase + mi * 16 + grp + half * 8;
                const size_t rb = (size_t)r * HID;
#pragma unroll
                for (int ni = 0; ni < 8; ++ni) {
                    const int c = col0 + ni * 8 + 2 * tig;
                    const size_t off = rb + c;
                    float v0 = d[mi][ni][half * 2 + 0] + bias0[ni];
                    float v1 = d[mi][ni][half * 2 + 1] + bias1[ni];

                    if (ep.mode == 0) {
                        *reinterpret_cast<uint32_t*>(ep.out_bf + off) =
                            packbf(tanh_fast(v0), tanh_fast(v1));
                    } else if (ep.mode == 1) {
                        const float2 yv = *reinterpret_cast<const float2*>(ep.yin + off);
                        v0 += yv.x; v1 += yv.y;
                        *reinterpret_cast<float2*>(ep.S_out + off) = make_float2(v0, v1);
                        *reinterpret_cast<uint32_t*>(ep.out_bf + off) = packbf(v0, v1);
                    } else {
                        const float2 sv = *reinterpret_cast<const float2*>(ep.S_in + off);
                        float a0 = ccur * v0, a1 = ccur * v1;
                        for (int q = 0; q < 5; ++q) {
                            if (q >= ep.nprev) break;
                            __nv_bfloat162 kk;
                            *reinterpret_cast<uint32_t*>(&kk) =
                                *reinterpret_cast<const uint32_t*>(ep.kp[q] + off);
                            const float cq = ep.c[q];
                            a0 += cq * __bfloat162float(kk.x);
                            a1 += cq * __bfloat162float(kk.y);
                        }
                        const float z0 = sv.x + h * a0;
                        const float z1 = sv.y + h * a1;
                        if (ep.k_out)
                            *reinterpret_cast<uint32_t*>(ep.k_out + off) = packbf(v0, v1);
                        *reinterpret_cast<uint32_t*>(ep.out_bf + off) = packbf(z0, z1);
                        if (ep.write_state)
                            *reinterpret_cast<float2*>(ep.S_out + off) = make_float2(z0, z1);
                    }
                }
            }
    }
}

// ============================================================================
// Prep kernels
// ============================================================================
__global__ void prep_w(const float* __restrict__ Wp, const float* __restrict__ W1,
                       const float* __restrict__ W2, const float* __restrict__ W3) {
    int idx = blockIdx.x * blockDim.x + threadIdx.x;
    if (idx < HID * HID) {
        int n = idx / HID, k = idx % HID;
        g_W1t[idx] = __float2bfloat16_rn(W1[k * HID + n]);
        g_W2t[idx] = __float2bfloat16_rn(W2[k * HID + n]);
        g_W3t[idx] = __float2bfloat16_rn(W3[k * HID + n]);
    }
    if (idx < HID * KPRJ) {
        int n = idx / KPRJ, j = idx % KPRJ;
        int ksrc = (j < IND) ? j : (j < 2 * IND) ? (j - IND) : (j - 2 * IND);
        float w = Wp[ksrc * HID + n];
        __nv_bfloat16 hi = __float2bfloat16_rn(w);
        if (j < 2 * IND)
            g_Wpt[idx] = hi;                                            // hi segments
        else
            g_Wpt[idx] = __float2bfloat16_rn(w - __bfloat162float(hi)); // lo segment
    }
}

__global__ void prep_u(const float* __restrict__ u) {
    int idx = blockIdx.x * blockDim.x + threadIdx.x;
    if (idx >= BD * IND) return;
    int row = idx / IND, c = idx % IND;
    float x = u[idx];
    __nv_bfloat16 hi = __float2bfloat16_rn(x);
    __nv_bfloat16 lo = __float2bfloat16_rn(x - __bfloat162float(hi));
    size_t base = (size_t)row * KPRJ;
    g_U[base + c]           = hi;
    g_U[base + IND + c]     = lo;
    g_U[base + 2 * IND + c] = hi;
}

// ============================================================================
// Host: 2 prep + 145 GEMM launches; final stage writes d_out directly
// ============================================================================
extern "C" void kernel_launch(void* const* d_in, const int* in_sizes, int n_in,
                              void* d_out, int out_size) {
    const float* y  = (const float*)d_in[0];
    const float* u  = (const float*)d_in[1];
    const float* Wp = (const float*)d_in[2];
    const float* bp = (const float*)d_in[3];
    const float* W1 = (const float*)d_in[4];
    const float* b1 = (const float*)d_in[5];
    const float* W2 = (const float*)d_in[6];
    const float* b2 = (const float*)d_in[7];
    const float* W3 = (const float*)d_in[8];
    const float* b3 = (const float*)d_in[9];
    float* out = (float*)d_out;

    cudaFuncSetAttribute(ode_gemm, cudaFuncAttributeMaxDynamicSharedMemorySize, SMEM_DYN);

    void* pv;
    cudaGetSymbolAddress(&pv, g_S);    float* S             = (float*)pv;
    cudaGetSymbolAddress(&pv, g_Sbf);  __nv_bfloat16* Sbf   = (__nv_bfloat16*)pv;
    cudaGetSymbolAddress(&pv, g_H1);   __nv_bfloat16* H1    = (__nv_bfloat16*)pv;
    cudaGetSymbolAddress(&pv, g_H2);   __nv_bfloat16* H2    = (__nv_bfloat16*)pv;
    cudaGetSymbolAddress(&pv, g_Karr); __nv_bfloat16* Kb    = (__nv_bfloat16*)pv;
    cudaGetSymbolAddress(&pv, g_U);    __nv_bfloat16* U     = (__nv_bfloat16*)pv;
    cudaGetSymbolAddress(&pv, g_W1t);  __nv_bfloat16* W1t   = (__nv_bfloat16*)pv;
    cudaGetSymbolAddress(&pv, g_W2t);  __nv_bfloat16* W2t   = (__nv_bfloat16*)pv;
    cudaGetSymbolAddress(&pv, g_W3t);  __nv_bfloat16* W3t   = (__nv_bfloat16*)pv;
    cudaGetSymbolAddress(&pv, g_Wpt);  __nv_bfloat16* Wpt   = (__nv_bfloat16*)pv;

    prep_w<<<(HID * KPRJ + 255) / 256, 256>>>(Wp, W1, W2, W3);
    prep_u<<<(BD * IND + 255) / 256, 256>>>(u);

    const dim3 grid(128, 4);

    // Projection: S = y + u@Wp + bp  (exact via hi/lo split, K=768)
    {
        EpiParams e; memset(&e, 0, sizeof(e));
        e.mode = 1; e.bias = bp; e.yin = y; e.S_out = S; e.out_bf = Sbf;
        ode_gemm<<<grid, 256, SMEM_DYN>>>(U, Wpt, KPRJ, e);
    }

    const float h = (float)(0.1 / 8.0);
    // Row j-1: stage-combine coefs after computing k_j (row 6 = 5th-order B weights)
    static const float RKC[6][6] = {
        {1.0f/5, 0, 0, 0, 0, 0},
        {3.0f/40, 9.0f/40, 0, 0, 0, 0},
        {44.0f/45, -56.0f/15, 32.0f/9, 0, 0, 0},
        {19372.0f/6561, -25360.0f/2187, 64448.0f/6561, -212.0f/729, 0, 0},
        {9017.0f/3168, -355.0f/33, 46732.0f/5247, 49.0f/176, -5103.0f/18656, 0},
        {35.0f/384, 0.0f, 500.0f/1113, 125.0f/192, -2187.0f/6784, 11.0f/84},
    };

    for (int st = 0; st < NSTEPS; ++st) {
        for (int j = 1; j <= 6; ++j) {
            // Layer 1: tanh(Sbf @ W1 + b1) -> H1
            {
                EpiParams e; memset(&e, 0, sizeof(e));
                e.mode = 0; e.bias = b1; e.out_bf = H1;
                ode_gemm<<<grid, 256, SMEM_DYN>>>(Sbf, W1t, HID, e);
            }
            // Layer 2: tanh(H1 @ W2 + b2) -> H2
            {
                EpiParams e; memset(&e, 0, sizeof(e));
                e.mode = 0; e.bias = b2; e.out_bf = H2;
                ode_gemm<<<grid, 256, SMEM_DYN>>>(H1, W2t, HID, e);
            }
            // Layer 3: k_j = H2 @ W3 + b3, fused RK stage combine
            {
                EpiParams e; memset(&e, 0, sizeof(e));
                e.mode = 2; e.bias = b3; e.h = h;
                e.S_in = S; e.out_bf = Sbf;
                e.nprev = j - 1;
                for (int q = 0; q < 5; ++q) e.kp[q] = Kb + (size_t)q * NN;
                for (int q = 0; q < 6; ++q) e.c[q] = RKC[j - 1][q];
                e.k_out = (j <= 5) ? (Kb + (size_t)(j - 1) * NN) : (__nv_bfloat16*)0;
                if (j == 6) {
                    e.write_state = 1;
                    e.S_out = (st == NSTEPS - 1) ? out : S;
                }
                ode_gemm<<<grid, 256, SMEM_DYN>>>(H2, W3t, HID, e);
            }
        }
    }
    (void)in_sizes; (void)n_in; (void)out_size;
}

// round 16
// speedup vs baseline: 1.9623x; 1.4657x over previous
#include <cuda_runtime.h>
#include <cuda_bf16.h>
#include <cstdint>
#include <cstring>

// ============================================================================
// Problem constants
// ============================================================================
#define BD     16384
#define HID    512
#define IND    256
#define KPRJ   768          // [u_hi | u_lo | u_hi] split-projection K
#define NSTEPS 8
#define NN     ((size_t)BD * (size_t)HID)

// ============================================================================
// Device scratch (__device__ globals: allocation-free rule)
// ============================================================================
__device__ float         g_S  [NN];            // fp32 RK state
__device__ __nv_bfloat16 g_Sbf[NN];            // bf16 stage input
__device__ __nv_bfloat16 g_H1 [NN];
__device__ __nv_bfloat16 g_H2 [NN];
__device__ __nv_bfloat16 g_Karr[5 * NN];       // k1..k5 (k6 consumed in-register)
__device__ __nv_bfloat16 g_U  [(size_t)BD * KPRJ];
__device__ __nv_bfloat16 g_W1t[HID * HID];     // [N,K] transposed weights (bf16)
__device__ __nv_bfloat16 g_W2t[HID * HID];
__device__ __nv_bfloat16 g_W3t[HID * HID];
__device__ __nv_bfloat16 g_Wpt[HID * KPRJ];

// ============================================================================
// PTX helpers (sm_80-class only: compiles under compute_103 virtual arch)
// ============================================================================
#define CP_ASYNC16(saddr, gptr) \
    asm volatile("cp.async.cg.shared.global [%0], [%1], 16;" \
        :: "r"(saddr), "l"(gptr) : "memory")

#define CP_COMMIT() asm volatile("cp.async.commit_group;" ::: "memory")

#define CP_WAIT(n)  asm volatile("cp.async.wait_group %0;" :: "n"(n) : "memory")

#define LDSM_X4(r, addr) \
    asm volatile("ldmatrix.sync.aligned.m8n8.x4.shared.b16 {%0,%1,%2,%3}, [%4];" \
        : "=r"((r)[0]), "=r"((r)[1]), "=r"((r)[2]), "=r"((r)[3]) : "r"(addr))

__device__ __forceinline__ uint32_t smem_to_u32(const void* smem_ptr) {
    uint32_t addr;
    asm("{ .reg .u64 tmp; cvta.to.shared.u64 tmp, %1; cvt.u32.u64 %0, tmp; }"
        : "=r"(addr) : "l"(smem_ptr));
    return addr;
}

__device__ __forceinline__ void mma_bf16(float* d, const uint32_t* a,
                                         uint32_t b0, uint32_t b1) {
    asm volatile(
        "mma.sync.aligned.m16n8k16.row.col.f32.bf16.bf16.f32 "
        "{%0,%1,%2,%3}, {%4,%5,%6,%7}, {%8,%9}, {%0,%1,%2,%3};"
        : "+f"(d[0]), "+f"(d[1]), "+f"(d[2]), "+f"(d[3])
        : "r"(a[0]), "r"(a[1]), "r"(a[2]), "r"(a[3]), "r"(b0), "r"(b1));
}

__device__ __forceinline__ float tanh_fast(float x) {
    float y;
    asm("tanh.approx.f32 %0, %1;" : "=f"(y) : "f"(x));
    return y;
}

__device__ __forceinline__ uint32_t packbf(float a, float b) {
    __nv_bfloat162 t = __floats2bfloat162_rn(a, b);
    return *reinterpret_cast<uint32_t*>(&t);
}

// SW128 xor swizzle on a tile-relative byte offset (rows of 128 bytes)
__device__ __forceinline__ uint32_t swz(uint32_t off) {
    return off ^ ((off >> 3) & 0x70u);
}

// ============================================================================
// Fused epilogue parameters
// ============================================================================
struct EpiParams {
    int   mode;          // 0 = tanh->bf16, 1 = proj (S=acc+bias+y), 2 = k-stage
    int   nprev;         // k-stage: number of previous k's
    int   write_state;   // k-stage: write fp32 state (j==6)
    float h;
    const float* bias;
    const float* yin;    // proj: y input
    const float* S_in;   // k-stage: base state
    float*       S_out;  // proj: g_S; k-stage j==6: g_S or d_out
    __nv_bfloat16*       out_bf;   // next-stage input / hidden activation
    __nv_bfloat16*       k_out;    // k-stage: store k_j (null for j==6)
    const __nv_bfloat16* kp[5];
    float c[6];          // c[0..nprev-1] prev-k coefs, c[nprev] current-k coef
};

// ============================================================================
// bf16 GEMM via mma.sync: D[16384,512] = A[16384,K] @ Wt[512,K]^T, fused epi
// grid (128, 4): CTA tile M=128 x N=128.  256 threads = 8 warps (4 M x 2 N),
// warp tile 32x64.  3-stage cp.async pipeline, K chunks of 64, 2 CTAs/SM.
// ks-slices software-pipelined with double-buffered ldmatrix fragments.
//
// Swizzle stepping identity (the R12 bug, now fixed): for base pre-swizzle
// offset x with bits [6:5] == 0 (row*128 + sl*16 qualifies) and kso = ks*32
// (bits [6:5] only):  swz(x + kso) == swz(x) ^ kso    (XOR, never ADD —
// swz(x) generally has bits [6:5] set by the XOR term, so ADD would carry
// into bit 7 and address a different row).
// ============================================================================
#define STAGES   3
#define SM_STAGE 32768        // A tile 16KB + B tile 16KB
#define SMEM_DYN (STAGES * SM_STAGE + 1024)

__global__ __launch_bounds__(256, 2)
void ode_gemm(const __nv_bfloat16* __restrict__ A,
              const __nv_bfloat16* __restrict__ Bw,
              int Ktot, EpiParams ep) {
    extern __shared__ char smem_raw[];
    const uint32_t sb = (smem_to_u32(smem_raw) + 1023u) & ~1023u;

    const int tid  = threadIdx.x;
    const int lane = tid & 31;
    const int wid  = tid >> 5;
    const int warp_m = wid >> 1;          // 0..3
    const int warp_n = wid & 1;           // 0..1
    const int mtile = blockIdx.x;
    const int ntile = blockIdx.y;

    const int KT = Ktot >> 6;             // 64-wide K chunks (8 or 12)

    // per-thread cp.async coords: thread -> (row = tid>>3 [+32*r], seg = tid&7)
    const int lrow = tid >> 3;
    const int lseg = tid & 7;
    const __nv_bfloat16* Abase = A  + (size_t)(mtile * 128) * Ktot + lseg * 8;
    const __nv_bfloat16* Bbase = Bw + (size_t)(ntile * 128) * Ktot + lseg * 8;

    // ---- async stage loader: 4 A rows + 4 B rows of 16B each ----
    auto issue = [&](int kt) {
        const uint32_t stg = sb + (uint32_t)(kt % STAGES) * SM_STAGE;
        const int k0 = kt * 64;
#pragma unroll
        for (int r = 0; r < 4; ++r) {
            const int row = lrow + r * 32;
            const uint32_t off = swz((uint32_t)(row * 128 + lseg * 16));
            CP_ASYNC16(stg + off,          Abase + (size_t)row * Ktot + k0);
            CP_ASYNC16(stg + 16384 + off,  Bbase + (size_t)row * Ktot + k0);
        }
    };

    float d[2][8][4];
#pragma unroll
    for (int mi = 0; mi < 2; ++mi)
#pragma unroll
        for (int ni = 0; ni < 8; ++ni)
#pragma unroll
            for (int e = 0; e < 4; ++e) d[mi][ni][e] = 0.0f;

    // ---- prologue: stages 0..STAGES-2 in flight ----
#pragma unroll
    for (int s = 0; s < STAGES - 1; ++s) {
        issue(s);
        CP_COMMIT();
    }

    // precomputed ldmatrix lane offsets
    const int a_rl = ((lane >> 3) & 1) * 8 + (lane & 7);   // A: row within 16
    const int a_sl = (lane >> 4);                          // A: +seg
    const int b_rl = ((lane >> 4) & 1) * 8 + (lane & 7);   // B: row within 16
    const int b_sl = ((lane >> 3) & 1);                    // B: +seg

    // base smem offsets for this warp's frags (stage base added later; per-ks
    // stepping via XOR with ks*32, see identity above)
    const uint32_t a_off0 = swz((uint32_t)((warp_m * 32 + a_rl) * 128 + a_sl * 16));
    const uint32_t a_off1 = swz((uint32_t)((warp_m * 32 + 16 + a_rl) * 128 + a_sl * 16));
    uint32_t b_off[4];
#pragma unroll
    for (int nb = 0; nb < 4; ++nb)
        b_off[nb] = swz((uint32_t)((warp_n * 64 + nb * 16 + b_rl) * 128 + b_sl * 16));

    // double-buffered fragments
    uint32_t afr[2][2][4];
    uint32_t bfr[2][4][4];

    // ---- mainloop: 1 sync/iter, ks-slices software-pipelined ----
    for (int kt = 0; kt < KT; ++kt) {
        CP_WAIT(STAGES - 2);                // stage kt resident
        __syncthreads();                    // publish stage kt; also proves all
                                            // warps done reading stage kt-1
        if (kt + STAGES - 1 < KT) issue(kt + STAGES - 1);
        CP_COMMIT();                        // unconditional: uniform accounting

        const uint32_t stg = sb + (uint32_t)(kt % STAGES) * SM_STAGE;
        const uint32_t aT = stg, bT = stg + 16384;

        // preload ks=0 fragments
        LDSM_X4(afr[0][0], aT + a_off0);
        LDSM_X4(afr[0][1], aT + a_off1);
#pragma unroll
        for (int nb = 0; nb < 4; ++nb)
            LDSM_X4(bfr[0][nb], bT + b_off[nb]);

#pragma unroll
        for (int ks = 0; ks < 4; ++ks) {
            const int cur = ks & 1;
            const int nxt = cur ^ 1;
            if (ks < 3) {
                const uint32_t kso = (uint32_t)((ks + 1) * 32);
                // XOR stepping: base addresses (aT/bT) are 1024-aligned and the
                // pre-swizzle offsets have bits [6:5] == 0, so
                // aT + (a_off ^ kso) == aT + swz(pre_off + kso).
                LDSM_X4(afr[nxt][0], aT + (a_off0 ^ kso));
                LDSM_X4(afr[nxt][1], aT + (a_off1 ^ kso));
#pragma unroll
                for (int nb = 0; nb < 4; ++nb)
                    LDSM_X4(bfr[nxt][nb], bT + (b_off[nb] ^ kso));
            }
#pragma unroll
            for (int mi = 0; mi < 2; ++mi)
#pragma unroll
                for (int nb = 0; nb < 4; ++nb) {
                    mma_bf16(d[mi][nb * 2],     afr[cur][mi], bfr[cur][nb][0], bfr[cur][nb][1]);
                    mma_bf16(d[mi][nb * 2 + 1], afr[cur][mi], bfr[cur][nb][2], bfr[cur][nb][3]);
                }
        }
        // no trailing __syncthreads: next iteration's top barrier protects
        // the stage that the next issue() overwrites.
    }

    // ---- fused epilogue ----
    {
        const int tig = lane & 3;
        const int grp = lane >> 2;
        const int col0 = ntile * 128 + warp_n * 64;
        const int rowbase = mtile * 128 + warp_m * 32;

        // bias pairs per ni
        float bias0[8], bias1[8];
#pragma unroll
        for (int ni = 0; ni < 8; ++ni) {
            const int c = col0 + ni * 8 + 2 * tig;
            bias0[ni] = __ldg(ep.bias + c);
            bias1[ni] = __ldg(ep.bias + c + 1);
        }

        const float ccur = ep.c[ep.nprev];
        const float h = ep.h;

#pragma unroll
        for (int mi = 0; mi < 2; ++mi)
#pragma unroll
            for (int half = 0; half < 2; ++half) {
                const int r = rowbase + mi * 16 + grp + half * 8;
                const size_t rb = (size_t)r * HID;
#pragma unroll
                for (int ni = 0; ni < 8; ++ni) {
                    const int c = col0 + ni * 8 + 2 * tig;
                    const size_t off = rb + c;
                    float v0 = d[mi][ni][half * 2 + 0] + bias0[ni];
                    float v1 = d[mi][ni][half * 2 + 1] + bias1[ni];

                    if (ep.mode == 0) {
                        *reinterpret_cast<uint32_t*>(ep.out_bf + off) =
                            packbf(tanh_fast(v0), tanh_fast(v1));
                    } else if (ep.mode == 1) {
                        const float2 yv = *reinterpret_cast<const float2*>(ep.yin + off);
                        v0 += yv.x; v1 += yv.y;
                        *reinterpret_cast<float2*>(ep.S_out + off) = make_float2(v0, v1);
                        *reinterpret_cast<uint32_t*>(ep.out_bf + off) = packbf(v0, v1);
                    } else {
                        const float2 sv = *reinterpret_cast<const float2*>(ep.S_in + off);
                        float a0 = ccur * v0, a1 = ccur * v1;
                        for (int q = 0; q < 5; ++q) {
                            if (q >= ep.nprev) break;
                            __nv_bfloat162 kk;
                            *reinterpret_cast<uint32_t*>(&kk) =
                                *reinterpret_cast<const uint32_t*>(ep.kp[q] + off);
                            const float cq = ep.c[q];
                            a0 += cq * __bfloat162float(kk.x);
                            a1 += cq * __bfloat162float(kk.y);
                        }
                        const float z0 = sv.x + h * a0;
                        const float z1 = sv.y + h * a1;
                        if (ep.k_out)
                            *reinterpret_cast<uint32_t*>(ep.k_out + off) = packbf(v0, v1);
                        *reinterpret_cast<uint32_t*>(ep.out_bf + off) = packbf(z0, z1);
                        if (ep.write_state)
                            *reinterpret_cast<float2*>(ep.S_out + off) = make_float2(z0, z1);
                    }
                }
            }
    }
}

// ============================================================================
// Prep kernels
// ============================================================================
__global__ void prep_w(const float* __restrict__ Wp, const float* __restrict__ W1,
                       const float* __restrict__ W2, const float* __restrict__ W3) {
    int idx = blockIdx.x * blockDim.x + threadIdx.x;
    if (idx < HID * HID) {
        int n = idx / HID, k = idx % HID;
        g_W1t[idx] = __float2bfloat16_rn(W1[k * HID + n]);
        g_W2t[idx] = __float2bfloat16_rn(W2[k * HID + n]);
        g_W3t[idx] = __float2bfloat16_rn(W3[k * HID + n]);
    }
    if (idx < HID * KPRJ) {
        int n = idx / KPRJ, j = idx % KPRJ;
        int ksrc = (j < IND) ? j : (j < 2 * IND) ? (j - IND) : (j - 2 * IND);
        float w = Wp[ksrc * HID + n];
        __nv_bfloat16 hi = __float2bfloat16_rn(w);
        if (j < 2 * IND)
            g_Wpt[idx] = hi;                                            // hi segments
        else
            g_Wpt[idx] = __float2bfloat16_rn(w - __bfloat162float(hi)); // lo segment
    }
}

__global__ void prep_u(const float* __restrict__ u) {
    int idx = blockIdx.x * blockDim.x + threadIdx.x;
    if (idx >= BD * IND) return;
    int row = idx / IND, c = idx % IND;
    float x = u[idx];
    __nv_bfloat16 hi = __float2bfloat16_rn(x);
    __nv_bfloat16 lo = __float2bfloat16_rn(x - __bfloat162float(hi));
    size_t base = (size_t)row * KPRJ;
    g_U[base + c]           = hi;
    g_U[base + IND + c]     = lo;
    g_U[base + 2 * IND + c] = hi;
}

// ============================================================================
// Host: 2 prep + 145 GEMM launches; final stage writes d_out directly
// ============================================================================
extern "C" void kernel_launch(void* const* d_in, const int* in_sizes, int n_in,
                              void* d_out, int out_size) {
    const float* y  = (const float*)d_in[0];
    const float* u  = (const float*)d_in[1];
    const float* Wp = (const float*)d_in[2];
    const float* bp = (const float*)d_in[3];
    const float* W1 = (const float*)d_in[4];
    const float* b1 = (const float*)d_in[5];
    const float* W2 = (const float*)d_in[6];
    const float* b2 = (const float*)d_in[7];
    const float* W3 = (const float*)d_in[8];
    const float* b3 = (const float*)d_in[9];
    float* out = (float*)d_out;

    cudaFuncSetAttribute(ode_gemm, cudaFuncAttributeMaxDynamicSharedMemorySize, SMEM_DYN);

    void* pv;
    cudaGetSymbolAddress(&pv, g_S);    float* S             = (float*)pv;
    cudaGetSymbolAddress(&pv, g_Sbf);  __nv_bfloat16* Sbf   = (__nv_bfloat16*)pv;
    cudaGetSymbolAddress(&pv, g_H1);   __nv_bfloat16* H1    = (__nv_bfloat16*)pv;
    cudaGetSymbolAddress(&pv, g_H2);   __nv_bfloat16* H2    = (__nv_bfloat16*)pv;
    cudaGetSymbolAddress(&pv, g_Karr); __nv_bfloat16* Kb    = (__nv_bfloat16*)pv;
    cudaGetSymbolAddress(&pv, g_U);    __nv_bfloat16* U     = (__nv_bfloat16*)pv;
    cudaGetSymbolAddress(&pv, g_W1t);  __nv_bfloat16* W1t   = (__nv_bfloat16*)pv;
    cudaGetSymbolAddress(&pv, g_W2t);  __nv_bfloat16* W2t   = (__nv_bfloat16*)pv;
    cudaGetSymbolAddress(&pv, g_W3t);  __nv_bfloat16* W3t   = (__nv_bfloat16*)pv;
    cudaGetSymbolAddress(&pv, g_Wpt);  __nv_bfloat16* Wpt   = (__nv_bfloat16*)pv;

    prep_w<<<(HID * KPRJ + 255) / 256, 256>>>(Wp, W1, W2, W3);
    prep_u<<<(BD * IND + 255) / 256, 256>>>(u);

    const dim3 grid(128, 4);

    // Projection: S = y + u@Wp + bp  (exact via hi/lo split, K=768)
    {
        EpiParams e; memset(&e, 0, sizeof(e));
        e.mode = 1; e.bias = bp; e.yin = y; e.S_out = S; e.out_bf = Sbf;
        ode_gemm<<<grid, 256, SMEM_DYN>>>(U, Wpt, KPRJ, e);
    }

    const float h = (float)(0.1 / 8.0);
    // Row j-1: stage-combine coefs after computing k_j (row 6 = 5th-order B weights)
    static const float RKC[6][6] = {
        {1.0f/5, 0, 0, 0, 0, 0},
        {3.0f/40, 9.0f/40, 0, 0, 0, 0},
        {44.0f/45, -56.0f/15, 32.0f/9, 0, 0, 0},
        {19372.0f/6561, -25360.0f/2187, 64448.0f/6561, -212.0f/729, 0, 0},
        {9017.0f/3168, -355.0f/33, 46732.0f/5247, 49.0f/176, -5103.0f/18656, 0},
        {35.0f/384, 0.0f, 500.0f/1113, 125.0f/192, -2187.0f/6784, 11.0f/84},
    };

    for (int st = 0; st < NSTEPS; ++st) {
        for (int j = 1; j <= 6; ++j) {
            // Layer 1: tanh(Sbf @ W1 + b1) -> H1
            {
                EpiParams e; memset(&e, 0, sizeof(e));
                e.mode = 0; e.bias = b1; e.out_bf = H1;
                ode_gemm<<<grid, 256, SMEM_DYN>>>(Sbf, W1t, HID, e);
            }
            // Layer 2: tanh(H1 @ W2 + b2) -> H2
            {
                EpiParams e; memset(&e, 0, sizeof(e));
                e.mode = 0; e.bias = b2; e.out_bf = H2;
                ode_gemm<<<grid, 256, SMEM_DYN>>>(H1, W2t, HID, e);
            }
            // Layer 3: k_j = H2 @ W3 + b3, fused RK stage combine
            {
                EpiParams e; memset(&e, 0, sizeof(e));
                e.mode = 2; e.bias = b3; e.h = h;
                e.S_in = S; e.out_bf = Sbf;
                e.nprev = j - 1;
                for (int q = 0; q < 5; ++q) e.kp[q] = Kb + (size_t)q * NN;
                for (int q = 0; q < 6; ++q) e.c[q] = RKC[j - 1][q];
                e.k_out = (j <= 5) ? (Kb + (size_t)(j - 1) * NN) : (__nv_bfloat16*)0;
                if (j == 6) {
                    e.write_state = 1;
                    e.S_out = (st == NSTEPS - 1) ? out : S;
                }
                ode_gemm<<<grid, 256, SMEM_DYN>>>(H2, W3t, HID, e);
            }
        }
    }
    (void)in_sizes; (void)n_in; (void)out_size;
}

// round 17
// speedup vs baseline: 1.9646x; 1.0012x over previous
#include <cuda_runtime.h>
#include <cuda_bf16.h>
#include <cstdint>

// ============================================================================
// Problem constants
// ============================================================================
#define BD     16384
#define HID    512
#define IND    256
#define KPRJ   768          // [u_hi | u_lo | u_hi] split-projection K
#define NSTEPS 8
#define NN     ((size_t)BD * (size_t)HID)
#define NPHASE 145          // 1 proj + 8 steps * 6 stages * 3 layers
#define NTILE  512          // 128 mtiles x 4 ntiles per phase

// ============================================================================
// Device scratch (__device__ globals: allocation-free rule)
// ============================================================================
__device__ float         g_S  [NN];            // fp32 RK state
__device__ __nv_bfloat16 g_Sbf[NN];            // bf16 stage input
__device__ __nv_bfloat16 g_H1 [NN];
__device__ __nv_bfloat16 g_H2 [NN];
__device__ __nv_bfloat16 g_Karr[5 * NN];       // k1..k5 (k6 consumed in-register)
__device__ __nv_bfloat16 g_U  [(size_t)BD * KPRJ];
__device__ __nv_bfloat16 g_W1t[HID * HID];     // [N,K] transposed weights (bf16)
__device__ __nv_bfloat16 g_W2t[HID * HID];
__device__ __nv_bfloat16 g_W3t[HID * HID];
__device__ __nv_bfloat16 g_Wpt[HID * KPRJ];

// grid-barrier state: one counter per inter-phase barrier, used once per
// launch; the last-exiting CTA zeroes everything so each replay starts clean.
__device__ unsigned g_bar[160];
__device__ unsigned g_exit;

// Dormand-Prince coefs: row j-1 = combine coefs applied after computing k_j
// (rows 0..4 = A-rows for stages 2..6; row 5 = 5th-order B weights)
__constant__ float RKC[6][6] = {
    {1.0f/5, 0, 0, 0, 0, 0},
    {3.0f/40, 9.0f/40, 0, 0, 0, 0},
    {44.0f/45, -56.0f/15, 32.0f/9, 0, 0, 0},
    {19372.0f/6561, -25360.0f/2187, 64448.0f/6561, -212.0f/729, 0, 0},
    {9017.0f/3168, -355.0f/33, 46732.0f/5247, 49.0f/176, -5103.0f/18656, 0},
    {35.0f/384, 0.0f, 500.0f/1113, 125.0f/192, -2187.0f/6784, 11.0f/84},
};

// ============================================================================
// PTX helpers (sm_80-class only: compiles under compute_103 virtual arch)
// ============================================================================
#define CP_ASYNC16(saddr, gptr) \
    asm volatile("cp.async.cg.shared.global [%0], [%1], 16;" \
        :: "r"(saddr), "l"(gptr) : "memory")

#define CP_COMMIT() asm volatile("cp.async.commit_group;" ::: "memory")

#define CP_WAIT(n)  asm volatile("cp.async.wait_group %0;" :: "n"(n) : "memory")

#define LDSM_X4(r, addr) \
    asm volatile("ldmatrix.sync.aligned.m8n8.x4.shared.b16 {%0,%1,%2,%3}, [%4];" \
        : "=r"((r)[0]), "=r"((r)[1]), "=r"((r)[2]), "=r"((r)[3]) : "r"(addr))

__device__ __forceinline__ uint32_t smem_to_u32(const void* smem_ptr) {
    uint32_t addr;
    asm("{ .reg .u64 tmp; cvta.to.shared.u64 tmp, %1; cvt.u32.u64 %0, tmp; }"
        : "=r"(addr) : "l"(smem_ptr));
    return addr;
}

__device__ __forceinline__ void mma_bf16(float* d, const uint32_t* a,
                                         uint32_t b0, uint32_t b1) {
    asm volatile(
        "mma.sync.aligned.m16n8k16.row.col.f32.bf16.bf16.f32 "
        "{%0,%1,%2,%3}, {%4,%5,%6,%7}, {%8,%9}, {%0,%1,%2,%3};"
        : "+f"(d[0]), "+f"(d[1]), "+f"(d[2]), "+f"(d[3])
        : "r"(a[0]), "r"(a[1]), "r"(a[2]), "r"(a[3]), "r"(b0), "r"(b1));
}

__device__ __forceinline__ float tanh_fast(float x) {
    float y;
    asm("tanh.approx.f32 %0, %1;" : "=f"(y) : "f"(x));
    return y;
}

__device__ __forceinline__ uint32_t packbf(float a, float b) {
    __nv_bfloat162 t = __floats2bfloat162_rn(a, b);
    return *reinterpret_cast<uint32_t*>(&t);
}

// SW128 xor swizzle on a tile-relative byte offset (rows of 128 bytes)
__device__ __forceinline__ uint32_t swz(uint32_t off) {
    return off ^ ((off >> 3) & 0x70u);
}

// ============================================================================
// Per-CTA shared phase descriptor (keeps mainloop register pressure down —
// the epilogue reloads these from smem instead of holding them in regs)
// ============================================================================
struct PhaseSh {
    const __nv_bfloat16* A;
    const __nv_bfloat16* Bw;
    const float* bias;
    const float* yin;
    const float* Sin;
    float*       Sout;
    __nv_bfloat16* outbf;
    __nv_bfloat16* kout;
    int mode;            // 0 = tanh->bf16, 1 = proj, 2 = k-stage combine
    int nprev;
    int wstate;
    int crow;
    int Ktot;
};

__device__ __forceinline__ void setup_phase(
    int p, PhaseSh& sh,
    const float* y, const float* bp, const float* b1,
    const float* b2, const float* b3, float* out)
{
    sh.yin = 0; sh.Sin = 0; sh.Sout = 0; sh.kout = 0;
    sh.nprev = 0; sh.wstate = 0; sh.crow = 0;
    if (p == 0) {
        sh.mode = 1; sh.A = g_U; sh.Bw = g_Wpt; sh.Ktot = KPRJ;
        sh.bias = bp; sh.yin = y; sh.Sout = g_S; sh.outbf = g_Sbf;
    } else {
        const int q = p - 1;
        const int st = q / 18;
        const int r  = q % 18;
        const int j  = r / 3 + 1;          // RK stage 1..6
        const int layer = r % 3;
        sh.Ktot = HID;
        if (layer == 0) {
            sh.mode = 0; sh.A = g_Sbf; sh.Bw = g_W1t; sh.bias = b1; sh.outbf = g_H1;
        } else if (layer == 1) {
            sh.mode = 0; sh.A = g_H1;  sh.Bw = g_W2t; sh.bias = b2; sh.outbf = g_H2;
        } else {
            sh.mode = 2; sh.A = g_H2;  sh.Bw = g_W3t; sh.bias = b3; sh.outbf = g_Sbf;
            sh.nprev = j - 1; sh.crow = j - 1; sh.Sin = g_S;
            sh.kout = (j <= 5) ? (g_Karr + (size_t)(j - 1) * NN) : (__nv_bfloat16*)0;
            if (j == 6) {
                sh.wstate = 1;
                sh.Sout = (st == NSTEPS - 1) ? out : g_S;
            }
        }
    }
}

// ============================================================================
// Persistent mega-kernel: 145 GEMM phases separated by grid-wide barriers.
// grid = 2 * #SM (co-resident by construction: <=128 regs via launch_bounds,
// 97KB smem -> 2 CTAs/SM, proven at occ=25.6% in prior rounds).
// GEMM core: CTA tile 128x128, 8 warps 4Mx2N, warp tile 32x64, 3-stage
// cp.async pipeline, frag double-buffering with XOR swizzle stepping.
// ============================================================================
#define STAGES   3
#define SM_STAGE 32768        // A tile 16KB + B tile 16KB
#define SMEM_DYN (STAGES * SM_STAGE + 1024)

__global__ __launch_bounds__(256, 2)
void ode_mega(const float* __restrict__ y,  const float* __restrict__ bp,
              const float* __restrict__ b1, const float* __restrict__ b2,
              const float* __restrict__ b3, float* __restrict__ out) {
    extern __shared__ char smem_raw[];
    const uint32_t sb = (smem_to_u32(smem_raw) + 1023u) & ~1023u;
    __shared__ PhaseSh ps;

    const int tid  = threadIdx.x;
    const int lane = tid & 31;
    const int wid  = tid >> 5;
    const int warp_m = wid >> 1;          // 0..3
    const int warp_n = wid & 1;           // 0..1
    const unsigned target = gridDim.x;

    // cp.async thread coords
    const int lrow = tid >> 3;
    const int lseg = tid & 7;

    // ldmatrix lane offsets
    const int a_rl = ((lane >> 3) & 1) * 8 + (lane & 7);
    const int a_sl = (lane >> 4);
    const int b_rl = ((lane >> 4) & 1) * 8 + (lane & 7);
    const int b_sl = ((lane >> 3) & 1);
    const uint32_t a_off0 = swz((uint32_t)((warp_m * 32 + a_rl) * 128 + a_sl * 16));
    const uint32_t a_off1 = swz((uint32_t)((warp_m * 32 + 16 + a_rl) * 128 + a_sl * 16));
    uint32_t b_off[4];
#pragma unroll
    for (int nb = 0; nb < 4; ++nb)
        b_off[nb] = swz((uint32_t)((warp_n * 64 + nb * 16 + b_rl) * 128 + b_sl * 16));

    if (tid == 0) setup_phase(0, ps, y, bp, b1, b2, b3, out);
    __syncthreads();

    for (int p = 0; p < NPHASE; ++p) {
        const __nv_bfloat16* A  = ps.A;
        const __nv_bfloat16* Bw = ps.Bw;
        const int Ktot = ps.Ktot;
        const int KT   = Ktot >> 6;

        for (int t = blockIdx.x; t < NTILE; t += gridDim.x) {
            const int mtile = t >> 2;
            const int ntile = t & 3;
            const __nv_bfloat16* Abase = A  + (size_t)(mtile * 128) * Ktot + lseg * 8;
            const __nv_bfloat16* Bbase = Bw + (size_t)(ntile * 128) * Ktot + lseg * 8;

            // async stage loader
            auto issue = [&](int kt) {
                const uint32_t stg = sb + (uint32_t)(kt % STAGES) * SM_STAGE;
                const int k0 = kt * 64;
#pragma unroll
                for (int r = 0; r < 4; ++r) {
                    const int row = lrow + r * 32;
                    const uint32_t off = swz((uint32_t)(row * 128 + lseg * 16));
                    CP_ASYNC16(stg + off,         Abase + (size_t)row * Ktot + k0);
                    CP_ASYNC16(stg + 16384 + off, Bbase + (size_t)row * Ktot + k0);
                }
            };

            float d[2][8][4];
#pragma unroll
            for (int mi = 0; mi < 2; ++mi)
#pragma unroll
                for (int ni = 0; ni < 8; ++ni)
#pragma unroll
                    for (int e = 0; e < 4; ++e) d[mi][ni][e] = 0.0f;

            // prologue
#pragma unroll
            for (int s = 0; s < STAGES - 1; ++s) { issue(s); CP_COMMIT(); }

            uint32_t afr[2][2][4];
            uint32_t bfr[2][4][4];

            for (int kt = 0; kt < KT; ++kt) {
                CP_WAIT(STAGES - 2);
                __syncthreads();
                if (kt + STAGES - 1 < KT) issue(kt + STAGES - 1);
                CP_COMMIT();

                const uint32_t stg = sb + (uint32_t)(kt % STAGES) * SM_STAGE;
                const uint32_t aT = stg, bT = stg + 16384;

                LDSM_X4(afr[0][0], aT + a_off0);
                LDSM_X4(afr[0][1], aT + a_off1);
#pragma unroll
                for (int nb = 0; nb < 4; ++nb)
                    LDSM_X4(bfr[0][nb], bT + b_off[nb]);

#pragma unroll
                for (int ks = 0; ks < 4; ++ks) {
                    const int cur = ks & 1;
                    const int nxt = cur ^ 1;
                    if (ks < 3) {
                        const uint32_t kso = (uint32_t)((ks + 1) * 32);
                        // XOR stepping (see R15): swz(x+kso) == swz(x)^kso
                        LDSM_X4(afr[nxt][0], aT + (a_off0 ^ kso));
                        LDSM_X4(afr[nxt][1], aT + (a_off1 ^ kso));
#pragma unroll
                        for (int nb = 0; nb < 4; ++nb)
                            LDSM_X4(bfr[nxt][nb], bT + (b_off[nb] ^ kso));
                    }
#pragma unroll
                    for (int mi = 0; mi < 2; ++mi)
#pragma unroll
                        for (int nb = 0; nb < 4; ++nb) {
                            mma_bf16(d[mi][nb * 2],     afr[cur][mi], bfr[cur][nb][0], bfr[cur][nb][1]);
                            mma_bf16(d[mi][nb * 2 + 1], afr[cur][mi], bfr[cur][nb][2], bfr[cur][nb][3]);
                        }
                }
                // no trailing sync: next iter's top barrier protects reuse
            }
            __syncthreads();   // tile done: all LDSM reads complete before the
                               // next tile's prologue overwrites stage smem

            // ---- fused epilogue (params from shared) ----
            {
                const int tig = lane & 3;
                const int grp = lane >> 2;
                const int col0 = ntile * 128 + warp_n * 64;
                const int rowbase = mtile * 128 + warp_m * 32;
                const int mode = ps.mode;

                float bias0[8], bias1[8];
#pragma unroll
                for (int ni = 0; ni < 8; ++ni) {
                    const int c = col0 + ni * 8 + 2 * tig;
                    bias0[ni] = __ldg(ps.bias + c);
                    bias1[ni] = __ldg(ps.bias + c + 1);
                }

                const int   nprev = ps.nprev;
                const float ccur  = RKC[ps.crow][nprev];
                const float h     = 0.0125f;   // 0.1 / 8

#pragma unroll
                for (int mi = 0; mi < 2; ++mi)
#pragma unroll
                    for (int half = 0; half < 2; ++half) {
                        const int r = rowbase + mi * 16 + grp + half * 8;
                        const size_t rb = (size_t)r * HID;
#pragma unroll
                        for (int ni = 0; ni < 8; ++ni) {
                            const int c = col0 + ni * 8 + 2 * tig;
                            const size_t off = rb + c;
                            float v0 = d[mi][ni][half * 2 + 0] + bias0[ni];
                            float v1 = d[mi][ni][half * 2 + 1] + bias1[ni];

                            if (mode == 0) {
                                *reinterpret_cast<uint32_t*>(ps.outbf + off) =
                                    packbf(tanh_fast(v0), tanh_fast(v1));
                            } else if (mode == 1) {
                                const float2 yv = *reinterpret_cast<const float2*>(ps.yin + off);
                                v0 += yv.x; v1 += yv.y;
                                *reinterpret_cast<float2*>(ps.Sout + off) = make_float2(v0, v1);
                                *reinterpret_cast<uint32_t*>(ps.outbf + off) = packbf(v0, v1);
                            } else {
                                const float2 sv = *reinterpret_cast<const float2*>(ps.Sin + off);
                                float a0 = ccur * v0, a1 = ccur * v1;
                                for (int q = 0; q < 5; ++q) {
                                    if (q >= nprev) break;
                                    __nv_bfloat162 kk;
                                    *reinterpret_cast<uint32_t*>(&kk) =
                                        *reinterpret_cast<const uint32_t*>(g_Karr + (size_t)q * NN + off);
                                    const float cq = RKC[ps.crow][q];
                                    a0 += cq * __bfloat162float(kk.x);
                                    a1 += cq * __bfloat162float(kk.y);
                                }
                                const float z0 = sv.x + h * a0;
                                const float z1 = sv.y + h * a1;
                                if (ps.kout)
                                    *reinterpret_cast<uint32_t*>(ps.kout + off) = packbf(v0, v1);
                                *reinterpret_cast<uint32_t*>(ps.outbf + off) = packbf(z0, z1);
                                if (ps.wstate)
                                    *reinterpret_cast<float2*>(ps.Sout + off) = make_float2(z0, z1);
                            }
                        }
                    }
            }
        }

        // ---- grid-wide barrier between phases (not after the last) ----
        if (p < NPHASE - 1) {
            __syncthreads();
            if (tid == 0) {
                __threadfence();                    // release our phase-p writes
                atomicAdd(&g_bar[p], 1u);
                unsigned v;
                for (;;) {
                    asm volatile("ld.acquire.gpu.global.u32 %0, [%1];"
                                 : "=r"(v) : "l"(&g_bar[p]) : "memory");
                    if (v >= target) break;
                    asm volatile("nanosleep.u32 128;");
                }
                setup_phase(p + 1, ps, y, bp, b1, b2, b3, out);
            }
            __syncthreads();                        // publish barrier + new ps
        }
    }

    // ---- exit: last CTA resets barrier state for the next graph replay ----
    __syncthreads();
    if (tid == 0) {
        __threadfence();
        const unsigned v = atomicAdd(&g_exit, 1u);
        if (v == target - 1) {
            for (int i = 0; i < 160; ++i) g_bar[i] = 0;
            __threadfence();
            g_exit = 0;
        }
    }
}

// ============================================================================
// Prep kernels
// ============================================================================
__global__ void prep_w(const float* __restrict__ Wp, const float* __restrict__ W1,
                       const float* __restrict__ W2, const float* __restrict__ W3) {
    int idx = blockIdx.x * blockDim.x + threadIdx.x;
    if (idx < HID * HID) {
        int n = idx / HID, k = idx % HID;
        g_W1t[idx] = __float2bfloat16_rn(W1[k * HID + n]);
        g_W2t[idx] = __float2bfloat16_rn(W2[k * HID + n]);
        g_W3t[idx] = __float2bfloat16_rn(W3[k * HID + n]);
    }
    if (idx < HID * KPRJ) {
        int n = idx / KPRJ, j = idx % KPRJ;
        int ksrc = (j < IND) ? j : (j < 2 * IND) ? (j - IND) : (j - 2 * IND);
        float w = Wp[ksrc * HID + n];
        __nv_bfloat16 hi = __float2bfloat16_rn(w);
        if (j < 2 * IND)
            g_Wpt[idx] = hi;                                            // hi segments
        else
            g_Wpt[idx] = __float2bfloat16_rn(w - __bfloat162float(hi)); // lo segment
    }
}

__global__ void prep_u(const float* __restrict__ u) {
    int idx = blockIdx.x * blockDim.x + threadIdx.x;
    if (idx >= BD * IND) return;
    int row = idx / IND, c = idx % IND;
    float x = u[idx];
    __nv_bfloat16 hi = __float2bfloat16_rn(x);
    __nv_bfloat16 lo = __float2bfloat16_rn(x - __bfloat162float(hi));
    size_t base = (size_t)row * KPRJ;
    g_U[base + c]           = hi;
    g_U[base + IND + c]     = lo;
    g_U[base + 2 * IND + c] = hi;
}

// ============================================================================
// Host: 3 launches total (prep_w, prep_u, mega)
// ============================================================================
extern "C" void kernel_launch(void* const* d_in, const int* in_sizes, int n_in,
                              void* d_out, int out_size) {
    const float* y  = (const float*)d_in[0];
    const float* u  = (const float*)d_in[1];
    const float* Wp = (const float*)d_in[2];
    const float* bp = (const float*)d_in[3];
    const float* b1 = (const float*)d_in[5];
    const float* W1 = (const float*)d_in[4];
    const float* W2 = (const float*)d_in[6];
    const float* b2 = (const float*)d_in[7];
    const float* W3 = (const float*)d_in[8];
    const float* b3 = (const float*)d_in[9];
    float* out = (float*)d_out;

    cudaFuncSetAttribute(ode_mega, cudaFuncAttributeMaxDynamicSharedMemorySize, SMEM_DYN);

    int smc = 148;
    cudaDeviceGetAttribute(&smc, cudaDevAttrMultiProcessorCount, 0);
    int grid = smc * 2;                 // co-resident with 2 CTAs/SM
    if (grid > NTILE) grid = NTILE;

    prep_w<<<(HID * KPRJ + 255) / 256, 256>>>(Wp, W1, W2, W3);
    prep_u<<<(BD * IND + 255) / 256, 256>>>(u);
    ode_mega<<<grid, 256, SMEM_DYN>>>(y, bp, b1, b2, b3, out);

    (void)in_sizes; (void)n_in; (void)out_size;
}